// round 6
// baseline (speedup 1.0000x reference)
#include <cuda_runtime.h>

// ---------------- problem constants (fixed by dataset) ----------------
#define NPIX 147456        // 384*384
#define W384 384
#define NNZC 1474560       // NPIX/2 * 20
#define NLOC 73728         // NPIX/2
#define KIU  5
#define CG_STEPS 30

#define TPB   512
#define NBLK  288          // 288*512 == NPIX exactly
#define MPB   256          // matting pixels per block (NLOC / NBLK)
#define NWARP (TPB / 32)
#define NGRP  16           // barrier groups (288/16 = 18 blocks per group)
#define GSZ   18

// ---------------- device scratch (static only) ----------------
__device__ int2  g_pairR[NNZC];        // CSR-sorted {col, val-bits}
__device__ int2  g_pairC[NNZC];        // CSC-sorted {row, val-bits}
__device__ int   g_ptrR[NPIX + 1];
__device__ int   g_ptrC[NPIX + 1];
__device__ int   g_cntR[NPIX];
__device__ int   g_cntC[NPIX];
__device__ int   g_tmpR[NPIX];
__device__ int   g_tmpC[NPIX];
__device__ int   g_btot[288];
__device__ int   g_boff[288];

__device__ float g_rs_cm[NPIX];
__device__ float g_D[NPIX];
__device__ float g_S45[45 * NLOC];     // symmetric matting blocks [t*NLOC + k]
__device__ float g_Wiu[KIU * NLOC];    // [l*NLOC + k]
__device__ int   g_iuNbT[KIU * NLOC];  // transposed neighbor indices
__device__ float g_r[NPIX];
__device__ float g_w[NPIX];            // w = A r accumulator
__device__ float g_Lv[NPIX];
__device__ double2 g_dotGD[NBLK];      // {gamma, deltaA} partials
__device__ double  g_dotD2[NBLK];      // delta partials (phase C)

// tree barrier state: per-group counters on distinct 256B lines + root + sense
__device__ unsigned g_gcnt[NGRP * 64];
__device__ unsigned g_root;
__device__ volatile unsigned g_sense;

// ---------------- helpers ----------------
__device__ __forceinline__ int OFF9(int i) {
    int a = i / 3, b = i % 3;
    return (a - 1) + (b - 1) * W384;
}
__device__ __forceinline__ int TIDX(int i, int j) {
    return 9 * i - (i * (i - 1)) / 2 + (j - i);
}

__device__ __forceinline__ double bred(double v, double* sm) {
    int lane = threadIdx.x & 31, w = threadIdx.x >> 5;
    #pragma unroll
    for (int o = 16; o > 0; o >>= 1) v += __shfl_down_sync(0xffffffffu, v, o);
    if (lane == 0) sm[w] = v;
    __syncthreads();
    if (w == 0) {
        v = (lane < NWARP) ? sm[lane] : 0.0;
        #pragma unroll
        for (int o = 8; o > 0; o >>= 1) v += __shfl_down_sync(0xffffu, v, o);
    }
    __syncthreads();
    return v; // valid on thread 0
}

__device__ __forceinline__ double2 bred2(double a, double b, double2* sm2) {
    int lane = threadIdx.x & 31, w = threadIdx.x >> 5;
    #pragma unroll
    for (int o = 16; o > 0; o >>= 1) {
        a += __shfl_down_sync(0xffffffffu, a, o);
        b += __shfl_down_sync(0xffffffffu, b, o);
    }
    if (lane == 0) sm2[w] = make_double2(a, b);
    __syncthreads();
    if (w == 0) {
        double2 t = (lane < NWARP) ? sm2[lane] : make_double2(0.0, 0.0);
        a = t.x; b = t.y;
        #pragma unroll
        for (int o = 8; o > 0; o >>= 1) {
            a += __shfl_down_sync(0xffffu, a, o);
            b += __shfl_down_sync(0xffffu, b, o);
        }
    }
    __syncthreads();
    return make_double2(a, b);
}

// two-level tree barrier: monotonic epoch counters (no reset race)
__device__ __forceinline__ void gbar(unsigned &ep) {
    ep++;
    __syncthreads();
    if (threadIdx.x == 0) {
        __threadfence();
        int grp = blockIdx.x & (NGRP - 1);
        unsigned v = atomicAdd(&g_gcnt[grp * 64], 1u);
        if (v == ep * GSZ - 1u) {
            unsigned rv = atomicAdd(&g_root, 1u);
            if (rv == ep * NGRP - 1u) {
                __threadfence();
                g_sense = ep;
            }
        }
        if (g_sense < ep) {
            while (g_sense < ep) { __nanosleep(32); }
        }
        __threadfence();
    }
    __syncthreads();
}

// ---------------- setup kernels ----------------
__global__ void k_z() {
    int i = blockIdx.x * blockDim.x + threadIdx.x;
    if (i < NPIX) {
        g_cntR[i] = 0; g_cntC[i] = 0; g_tmpR[i] = 0; g_tmpC[i] = 0;
        g_rs_cm[i] = 0.f; g_D[i] = 0.f;
    }
    if (i < NGRP * 64) g_gcnt[i] = 0u;
    if (i == 0) { g_root = 0u; g_sense = 0u; }
}

__global__ void k_cnt(const float* __restrict__ CMw, const float* __restrict__ Wd,
                      const int* __restrict__ row, const int* __restrict__ col) {
    int k = blockIdx.x * blockDim.x + threadIdx.x;
    if (k >= NNZC) return;
    int r = row[k], c = col[k];
    float cv = CMw[r] * Wd[k];
    atomicAdd(&g_rs_cm[r], cv);
    atomicAdd(&g_cntR[r], 1);
    atomicAdd(&g_cntC[c], 1);
}

// 288 blocks x 1024: blocks 0..143 scan cntR, 144..287 scan cntC (within-block)
__global__ void k_scanA() {
    __shared__ int sm[1024];
    int half = blockIdx.x / 144;
    int blk  = blockIdx.x % 144;
    int gi   = blk * 1024 + threadIdx.x;
    int* cnt = half ? g_cntC : g_cntR;
    int* ptr = half ? g_ptrC : g_ptrR;
    int v = cnt[gi];
    sm[threadIdx.x] = v;
    __syncthreads();
    for (int o = 1; o < 1024; o <<= 1) {
        int t = (threadIdx.x >= o) ? sm[threadIdx.x - o] : 0;
        __syncthreads();
        sm[threadIdx.x] += t;
        __syncthreads();
    }
    ptr[gi] = sm[threadIdx.x] - v;
    if (threadIdx.x == 1023) g_btot[blockIdx.x] = sm[1023];
}

__global__ void k_scanB() {
    __shared__ int sm[288];
    int t = threadIdx.x;
    int v = (t < 288) ? g_btot[t] : 0;
    if (t < 288) sm[t] = v;
    __syncthreads();
    for (int o = 1; o < 288; o <<= 1) {
        int add = 0;
        if (t < 288 && t >= o) add = sm[t - o];
        __syncthreads();
        if (t < 288) sm[t] += add;
        __syncthreads();
    }
    if (t < 288) {
        int ex = sm[t] - v;
        int base = (t >= 144) ? sm[143] : 0;
        g_boff[t] = ex - base;
    }
}

__global__ void k_scanC() {
    int half = blockIdx.x / 144;
    int blk  = blockIdx.x % 144;
    int gi   = blk * 1024 + threadIdx.x;
    int* ptr = half ? g_ptrC : g_ptrR;
    ptr[gi] += g_boff[blockIdx.x];
    if (blockIdx.x == 0 && threadIdx.x == 0) {
        g_ptrR[NPIX] = NNZC;
        g_ptrC[NPIX] = NNZC;
    }
}

__global__ void k_scatter(const float* __restrict__ CMw, const float* __restrict__ Wd,
                          const int* __restrict__ row, const int* __restrict__ col) {
    int k = blockIdx.x * blockDim.x + threadIdx.x;
    if (k >= NNZC) return;
    int r = row[k], c = col[k];
    int vb = __float_as_int(CMw[r] * Wd[k]);
    int p1 = g_ptrR[r] + atomicAdd(&g_tmpR[r], 1);
    g_pairR[p1] = make_int2(c, vb);
    int p2 = g_ptrC[c] + atomicAdd(&g_tmpC[c], 1);
    g_pairC[p2] = make_int2(r, vb);
}

// fused: matting blocks (p2) + IU weights (p3) + diagonal/data init (p4)
__global__ void k_prep(const float* __restrict__ LOCw, const float* __restrict__ LF,
                       const int* __restrict__ inInd,
                       const float* __restrict__ IUw, const float* __restrict__ IUf,
                       const int* __restrict__ iuInd, const int* __restrict__ nbInd,
                       const float* __restrict__ KUw, const float* __restrict__ kToUconf,
                       const float* __restrict__ known, const float* __restrict__ kToU,
                       const float* __restrict__ lmbda) {
    int i = blockIdx.x * blockDim.x + threadIdx.x;
    if (i < NPIX) {
        float dk = KUw[i] * kToUconf[i] + lmbda[0] * known[i];
        float b  = dk * kToU[i];
        atomicAdd(&g_D[i], dk);
        g_r[i] = b;     // r0 = b (x0 = 0)
    }
    if (i < NLOC) {
        int m = i;
        // matting symmetric blocks
        {
            int ind = inInd[m];
            float w = LOCw[ind];
            float rs[9];
            #pragma unroll
            for (int q = 0; q < 9; q++) rs[q] = 0.f;
            #pragma unroll
            for (int a = 0; a < 9; a++) {
                #pragma unroll
                for (int b2 = a; b2 < 9; b2++) {
                    float s = 0.5f * w * (LF[(b2 * 9 + a) * NLOC + m] + LF[(a * 9 + b2) * NLOC + m]);
                    g_S45[TIDX(a, b2) * NLOC + m] = s;
                    rs[a] += s;
                    if (b2 > a) rs[b2] += s;
                }
            }
            #pragma unroll
            for (int q = 0; q < 9; q++) atomicAdd(&g_D[ind + OFF9(q)], rs[q]);
        }
        // IU weights
        {
            int ind = iuInd[m];
            float w = IUw[ind];
            #pragma unroll
            for (int l = 0; l < KIU; l++) {
                float wv = 0.5f * w * IUf[m * KIU + l];
                int nb = nbInd[m * KIU + l];
                g_Wiu[l * NLOC + m] = wv;
                g_iuNbT[l * NLOC + m] = nb;
                atomicAdd(&g_D[ind], wv);
                atomicAdd(&g_D[nb], wv);
            }
        }
    }
}

// ---------------- persistent single-reduction CG kernel ----------------
__global__ void __launch_bounds__(TPB, 2) k_cg(
    float* __restrict__ x,
    const int* __restrict__ locInd,
    const int* __restrict__ iuInd)
{
    __shared__ double2 sm2[NWARP];
    __shared__ double sred[NWARP];
    __shared__ double s_alpha, s_beta, s_gamma_prev, s_alpha_prev;
    const int tid  = threadIdx.x;
    const int gtid = blockIdx.x * TPB + tid;     // always < NPIX
    const int m    = blockIdx.x * MPB + tid;     // matting pixel if tid < MPB
    unsigned ep = 0;

    float r_reg = g_r[gtid];
    float p_reg = 0.f, s_reg = 0.f, x_reg = 0.f;
    const float rc = g_rs_cm[gtid];
    const float Di = g_D[gtid];

    for (int it = 0; it < CG_STEPS; ++it) {
        // ---- Phase A: CSR gather -> Lv -> w_init; gamma/delta partials
        {
            int b0 = g_ptrR[gtid], b1 = g_ptrR[gtid + 1];
            float acc = 0.f;
            int k = b0;
            for (; k + 4 <= b1; k += 4) {
                int2 e0 = g_pairR[k],     e1 = g_pairR[k + 1];
                int2 e2 = g_pairR[k + 2], e3 = g_pairR[k + 3];
                acc += __int_as_float(e0.y) * g_r[e0.x]
                     + __int_as_float(e1.y) * g_r[e1.x]
                     + __int_as_float(e2.y) * g_r[e2.x]
                     + __int_as_float(e3.y) * g_r[e3.x];
            }
            for (; k < b1; k++) {
                int2 e = g_pairR[k];
                acc += __int_as_float(e.y) * g_r[e.x];
            }
            float lv = rc * r_reg - acc;
            g_Lv[gtid] = lv;
            float wi = rc * lv + Di * r_reg;
            g_w[gtid] = wi;
            double2 gd = bred2((double)r_reg * (double)r_reg,
                               (double)r_reg * (double)wi, sm2);
            if (tid == 0) g_dotGD[blockIdx.x] = gd;
        }
        gbar(ep);

        // ---- Phase C: CSC gather + matting + IU scatters; delta partials
        {
            double dD = 0.0;
            {
                int b0 = g_ptrC[gtid], b1 = g_ptrC[gtid + 1];
                float acc = 0.f;
                int k = b0;
                for (; k + 4 <= b1; k += 4) {
                    int2 e0 = g_pairC[k],     e1 = g_pairC[k + 1];
                    int2 e2 = g_pairC[k + 2], e3 = g_pairC[k + 3];
                    acc += __int_as_float(e0.y) * g_Lv[e0.x]
                         + __int_as_float(e1.y) * g_Lv[e1.x]
                         + __int_as_float(e2.y) * g_Lv[e2.x]
                         + __int_as_float(e3.y) * g_Lv[e3.x];
                }
                for (; k < b1; k++) {
                    int2 e = g_pairC[k];
                    acc += __int_as_float(e.y) * g_Lv[e.x];
                }
                atomicAdd(&g_w[gtid], -acc);
                dD -= (double)acc * (double)r_reg;
            }
            if (tid < MPB) {
                // symmetric 9x9 matting block
                int ind = locInd[m];
                float pn[9], acc9[9];
                #pragma unroll
                for (int j = 0; j < 9; j++) { pn[j] = g_r[ind + OFF9(j)]; acc9[j] = 0.f; }
                #pragma unroll
                for (int i9 = 0; i9 < 9; i9++) {
                    #pragma unroll
                    for (int j9 = i9; j9 < 9; j9++) {
                        float v = g_S45[TIDX(i9, j9) * NLOC + m];
                        acc9[i9] += v * pn[j9];
                        if (j9 > i9) acc9[j9] += v * pn[i9];
                    }
                }
                #pragma unroll
                for (int i9 = 0; i9 < 9; i9++) {
                    atomicAdd(&g_w[ind + OFF9(i9)], -acc9[i9]);
                    dD -= (double)acc9[i9] * (double)pn[i9];
                }
                // IU KNN
                int ind2 = iuInd[m];
                float rind = g_r[ind2];
                float acc2 = 0.f;
                #pragma unroll
                for (int l = 0; l < KIU; l++) {
                    float wv = g_Wiu[l * NLOC + m];
                    int nb   = g_iuNbT[l * NLOC + m];
                    float rnb = g_r[nb];
                    acc2 += wv * rnb;
                    atomicAdd(&g_w[nb], -wv * rind);
                    dD -= (double)(wv * rind) * (double)rnb;
                }
                atomicAdd(&g_w[ind2], -acc2);
                dD -= (double)acc2 * (double)rind;
            }
            dD = bred(dD, sred);
            if (tid == 0) g_dotD2[blockIdx.x] = dD;
        }
        gbar(ep);

        // ---- Phase U: reduce gamma/delta; alpha,beta; register-resident update
        {
            double gamma = 0.0, delta = 0.0;
            if (tid < NBLK) {
                double2 gd = g_dotGD[tid];
                gamma = gd.x;
                delta = gd.y + g_dotD2[tid];
            }
            double2 gd = bred2(gamma, delta, sm2);
            if (tid == 0) {
                gamma = gd.x; delta = gd.y;
                double beta, alpha;
                if (it == 0) {
                    beta = 0.0;
                    alpha = gamma / delta;
                } else {
                    beta = gamma / s_gamma_prev;
                    alpha = gamma / (delta - beta * gamma / s_alpha_prev);
                }
                s_alpha = alpha; s_beta = beta;
                s_gamma_prev = gamma; s_alpha_prev = alpha;
            }
            __syncthreads();
            float alpha = (float)s_alpha;
            float beta  = (float)s_beta;
            float wi = g_w[gtid];
            if (it == 0) { p_reg = r_reg; s_reg = wi; }
            else {
                p_reg = r_reg + beta * p_reg;
                s_reg = wi + beta * s_reg;
            }
            x_reg += alpha * p_reg;
            r_reg = r_reg - alpha * s_reg;
            g_r[gtid] = r_reg;
            if (it == CG_STEPS - 1) x[gtid] = x_reg;
        }
        if (it + 1 < CG_STEPS) gbar(ep);
    }
}

// ---------------- host launch ----------------
extern "C" void kernel_launch(void* const* d_in, const int* in_sizes, int n_in,
                              void* d_out, int out_size) {
    const float* CMw    = (const float*)d_in[0];
    const float* LOCw   = (const float*)d_in[1];
    const float* IUw    = (const float*)d_in[2];
    const float* KUw    = (const float*)d_in[3];
    const float* lmbda  = (const float*)d_in[4];
    const float* kToUcf = (const float*)d_in[5];
    const float* known  = (const float*)d_in[6];
    const float* kToU   = (const float*)d_in[7];
    const float* Wd     = (const float*)d_in[8];
    const float* LF     = (const float*)d_in[9];
    const float* IUf    = (const float*)d_in[10];
    const int*   wrow   = (const int*)d_in[11];
    const int*   wcol   = (const int*)d_in[12];
    const int*   locInd = (const int*)d_in[13];
    const int*   iuInd  = (const int*)d_in[14];
    const int*   iuNb   = (const int*)d_in[15];
    float* x = (float*)d_out;

    const int gN   = (NPIX + 255) / 256;
    const int gNNZ = (NNZC + 255) / 256;

    k_z<<<gN, 256>>>();
    k_cnt<<<gNNZ, 256>>>(CMw, Wd, wrow, wcol);
    k_scanA<<<288, 1024>>>();
    k_scanB<<<1, 320>>>();
    k_scanC<<<288, 1024>>>();
    k_scatter<<<gNNZ, 256>>>(CMw, Wd, wrow, wcol);
    k_prep<<<gN, 256>>>(LOCw, LF, locInd, IUw, IUf, iuInd, iuNb,
                        KUw, kToUcf, known, kToU, lmbda);
    k_cg<<<NBLK, TPB>>>(x, locInd, iuInd);
}

// round 7
// speedup vs baseline: 1.0147x; 1.0147x over previous
#include <cuda_runtime.h>

// ---------------- problem constants (fixed by dataset) ----------------
#define NPIX 147456        // 384*384
#define W384 384
#define NNZC 1474560       // NPIX/2 * 20
#define NLOC 73728         // NPIX/2
#define KIU  5
#define CG_STEPS 30

#define TPB   512
#define NBLK  288          // 288*512 == NPIX exactly
#define MPB   256          // matting pixels per block (NLOC / NBLK)
#define NWARP (TPB / 32)
#define EPB   (NNZC / NBLK)   // COO entries per block = 5120

// ---------------- device scratch (static only; zero-initialized) ----------------
__device__ int2  g_pairR[NNZC];        // CSR-sorted {col, val-bits}
__device__ int2  g_pairC[NNZC];        // CSC-sorted {row, val-bits}
__device__ int   g_ptrR[NPIX + 1];
__device__ int   g_ptrC[NPIX + 1];
__device__ int   g_cntR[NPIX];
__device__ int   g_cntC[NPIX];
__device__ int   g_tmpR[NPIX];
__device__ int   g_tmpC[NPIX];
__device__ int2  g_btot2[NBLK];

__device__ float g_rs_cm[NPIX];
__device__ float g_D[NPIX];
__device__ float g_S45[45 * NLOC];     // symmetric matting blocks [t*NLOC + k]
__device__ float g_Wiu[KIU * NLOC];    // [l*NLOC + k]
__device__ int   g_iuNbT[KIU * NLOC];  // transposed neighbor indices
__device__ float g_r[NPIX];
__device__ float g_w[NPIX];            // w = A r accumulator
__device__ float g_Lv[NPIX];
__device__ double2 g_dotGD[NBLK];      // {gamma, deltaA} partials
__device__ double  g_dotD2[NBLK];      // delta partials (phase C)

__device__ unsigned g_count;
__device__ volatile unsigned g_sense;
__device__ unsigned g_exit;

// ---------------- helpers ----------------
__device__ __forceinline__ int OFF9(int i) {
    int a = i / 3, b = i % 3;
    return (a - 1) + (b - 1) * W384;
}
__device__ __forceinline__ int TIDX(int i, int j) {
    return 9 * i - (i * (i - 1)) / 2 + (j - i);
}

__device__ __forceinline__ double bred(double v, double* sm) {
    int lane = threadIdx.x & 31, w = threadIdx.x >> 5;
    #pragma unroll
    for (int o = 16; o > 0; o >>= 1) v += __shfl_down_sync(0xffffffffu, v, o);
    if (lane == 0) sm[w] = v;
    __syncthreads();
    if (w == 0) {
        v = (lane < NWARP) ? sm[lane] : 0.0;
        #pragma unroll
        for (int o = 8; o > 0; o >>= 1) v += __shfl_down_sync(0xffffu, v, o);
    }
    __syncthreads();
    return v; // valid on thread 0
}

__device__ __forceinline__ double2 bred2(double a, double b, double2* sm2) {
    int lane = threadIdx.x & 31, w = threadIdx.x >> 5;
    #pragma unroll
    for (int o = 16; o > 0; o >>= 1) {
        a += __shfl_down_sync(0xffffffffu, a, o);
        b += __shfl_down_sync(0xffffffffu, b, o);
    }
    if (lane == 0) sm2[w] = make_double2(a, b);
    __syncthreads();
    if (w == 0) {
        double2 t = (lane < NWARP) ? sm2[lane] : make_double2(0.0, 0.0);
        a = t.x; b = t.y;
        #pragma unroll
        for (int o = 8; o > 0; o >>= 1) {
            a += __shfl_down_sync(0xffffu, a, o);
            b += __shfl_down_sync(0xffffu, b, o);
        }
    }
    __syncthreads();
    return make_double2(a, b);
}

// single-counter sense barrier (state self-resets; g_sense reset at kernel exit)
__device__ __forceinline__ void gbar(unsigned &ep) {
    ep++;
    __syncthreads();
    if (threadIdx.x == 0) {
        __threadfence();
        if (atomicAdd(&g_count, 1u) == NBLK - 1) {
            g_count = 0;
            __threadfence();
            g_sense = ep;
        } else {
            while (g_sense != ep) { __nanosleep(32); }
            __threadfence();
        }
    }
    __syncthreads();
}

// ---------------- single persistent kernel: setup + CG ----------------
__global__ void __launch_bounds__(TPB, 2) k_all(
    float* __restrict__ x,
    const float* __restrict__ CMw,  const float* __restrict__ LOCw,
    const float* __restrict__ IUw,  const float* __restrict__ KUw,
    const float* __restrict__ lmbda,
    const float* __restrict__ kToUcf, const float* __restrict__ known,
    const float* __restrict__ kToU, const float* __restrict__ Wd,
    const float* __restrict__ LF,   const float* __restrict__ IUf,
    const int* __restrict__ wrow,   const int* __restrict__ wcol,
    const int* __restrict__ locInd, const int* __restrict__ iuInd,
    const int* __restrict__ iuNb)
{
    __shared__ int2   s_scan[TPB];
    __shared__ double2 sm2[NWARP];
    __shared__ double sred[NWARP];
    __shared__ int2   s_off;
    __shared__ double s_alpha, s_beta, s_gamma_prev, s_alpha_prev;

    const int tid  = threadIdx.x;
    const int gtid = blockIdx.x * TPB + tid;     // always < NPIX
    const int m    = blockIdx.x * MPB + tid;     // matting pixel if tid < MPB
    const int ebase = blockIdx.x * EPB;
    unsigned ep = 0;

    // ---- P0: zero working arrays (each thread owns one pixel slot)
    g_cntR[gtid] = 0; g_cntC[gtid] = 0; g_tmpR[gtid] = 0; g_tmpC[gtid] = 0;
    g_rs_cm[gtid] = 0.f; g_D[gtid] = 0.f;
    gbar(ep);

    // ---- P1: COO counts + rowsums, plus all precompute (matting, IU, data term)
    for (int e = tid; e < EPB; e += TPB) {
        int k = ebase + e;
        int r = wrow[k], c = wcol[k];
        float cv = CMw[r] * Wd[k];
        atomicAdd(&g_rs_cm[r], cv);
        atomicAdd(&g_cntR[r], 1);
        atomicAdd(&g_cntC[c], 1);
    }
    float r_reg;
    {
        float dk = KUw[gtid] * kToUcf[gtid] + lmbda[0] * known[gtid];
        r_reg = dk * kToU[gtid];
        g_r[gtid] = r_reg;
        atomicAdd(&g_D[gtid], dk);
    }
    if (tid < MPB) {
        // matting symmetric blocks
        {
            int ind = locInd[m];
            float w = LOCw[ind];
            float rs[9];
            #pragma unroll
            for (int q = 0; q < 9; q++) rs[q] = 0.f;
            #pragma unroll
            for (int a = 0; a < 9; a++) {
                #pragma unroll
                for (int b2 = a; b2 < 9; b2++) {
                    float s = 0.5f * w * (LF[(b2 * 9 + a) * NLOC + m] + LF[(a * 9 + b2) * NLOC + m]);
                    g_S45[TIDX(a, b2) * NLOC + m] = s;
                    rs[a] += s;
                    if (b2 > a) rs[b2] += s;
                }
            }
            #pragma unroll
            for (int q = 0; q < 9; q++) atomicAdd(&g_D[ind + OFF9(q)], rs[q]);
        }
        // IU weights
        {
            int ind = iuInd[m];
            float w = IUw[ind];
            #pragma unroll
            for (int l = 0; l < KIU; l++) {
                float wv = 0.5f * w * IUf[m * KIU + l];
                int nb = iuNb[m * KIU + l];
                g_Wiu[l * NLOC + m] = wv;
                g_iuNbT[l * NLOC + m] = nb;
                atomicAdd(&g_D[ind], wv);
                atomicAdd(&g_D[nb], wv);
            }
        }
    }
    gbar(ep);

    // ---- P2: block-local inclusive scan of {cntR, cntC}
    int2 myc = make_int2(g_cntR[gtid], g_cntC[gtid]);
    s_scan[tid] = myc;
    __syncthreads();
    for (int o = 1; o < TPB; o <<= 1) {
        int2 t = (tid >= o) ? s_scan[tid - o] : make_int2(0, 0);
        __syncthreads();
        s_scan[tid].x += t.x;
        s_scan[tid].y += t.y;
        __syncthreads();
    }
    int2 incl = s_scan[tid];
    int exR = incl.x - myc.x, exC = incl.y - myc.y;
    if (tid == TPB - 1) g_btot2[blockIdx.x] = incl;
    gbar(ep);

    // ---- P3: block offsets (sum of totals of preceding blocks) + write ptr
    {
        int2 v = (tid < blockIdx.x) ? g_btot2[tid] : make_int2(0, 0);
        int lane = tid & 31, w = tid >> 5;
        #pragma unroll
        for (int o = 16; o > 0; o >>= 1) {
            v.x += __shfl_down_sync(0xffffffffu, v.x, o);
            v.y += __shfl_down_sync(0xffffffffu, v.y, o);
        }
        __shared__ int2 sw[NWARP];
        if (lane == 0) sw[w] = v;
        __syncthreads();
        if (w == 0) {
            int2 t = (lane < NWARP) ? sw[lane] : make_int2(0, 0);
            #pragma unroll
            for (int o = 8; o > 0; o >>= 1) {
                t.x += __shfl_down_sync(0xffffu, t.x, o);
                t.y += __shfl_down_sync(0xffffu, t.y, o);
            }
            if (lane == 0) s_off = t;
        }
        __syncthreads();
        g_ptrR[gtid] = exR + s_off.x;
        g_ptrC[gtid] = exC + s_off.y;
        if (gtid == 0) { g_ptrR[NPIX] = NNZC; g_ptrC[NPIX] = NNZC; }
    }
    gbar(ep);

    // ---- P4: scatter into CSR/CSC pair arrays
    for (int e = tid; e < EPB; e += TPB) {
        int k = ebase + e;
        int r = wrow[k], c = wcol[k];
        int vb = __float_as_int(CMw[r] * Wd[k]);
        int p1 = g_ptrR[r] + atomicAdd(&g_tmpR[r], 1);
        g_pairR[p1] = make_int2(c, vb);
        int p2 = g_ptrC[c] + atomicAdd(&g_tmpC[c], 1);
        g_pairC[p2] = make_int2(r, vb);
    }
    gbar(ep);

    // ---- loop-invariant values
    const float rc = g_rs_cm[gtid];
    const float Di = g_D[gtid];
    const int rb0 = g_ptrR[gtid], rb1 = g_ptrR[gtid + 1];
    const int cb0 = g_ptrC[gtid], cb1 = g_ptrC[gtid + 1];
    float p_reg = 0.f, s_reg = 0.f, x_reg = 0.f;

    // ---- CG iterations (single-reduction Chronopoulos-Gear)
    for (int it = 0; it < CG_STEPS; ++it) {
        // Phase A: CSR gather -> Lv -> w_init; gamma/delta partials
        {
            float acc = 0.f;
            int k = rb0;
            for (; k + 4 <= rb1; k += 4) {
                int2 e0 = g_pairR[k],     e1 = g_pairR[k + 1];
                int2 e2 = g_pairR[k + 2], e3 = g_pairR[k + 3];
                acc += __int_as_float(e0.y) * g_r[e0.x]
                     + __int_as_float(e1.y) * g_r[e1.x]
                     + __int_as_float(e2.y) * g_r[e2.x]
                     + __int_as_float(e3.y) * g_r[e3.x];
            }
            for (; k < rb1; k++) {
                int2 e = g_pairR[k];
                acc += __int_as_float(e.y) * g_r[e.x];
            }
            float lv = rc * r_reg - acc;
            g_Lv[gtid] = lv;
            float wi = rc * lv + Di * r_reg;
            g_w[gtid] = wi;
            double2 gd = bred2((double)r_reg * (double)r_reg,
                               (double)r_reg * (double)wi, sm2);
            if (tid == 0) g_dotGD[blockIdx.x] = gd;
        }
        gbar(ep);

        // Phase C: CSC gather + matting + IU scatters; delta partials
        {
            double dD = 0.0;
            {
                float acc = 0.f;
                int k = cb0;
                for (; k + 4 <= cb1; k += 4) {
                    int2 e0 = g_pairC[k],     e1 = g_pairC[k + 1];
                    int2 e2 = g_pairC[k + 2], e3 = g_pairC[k + 3];
                    acc += __int_as_float(e0.y) * g_Lv[e0.x]
                         + __int_as_float(e1.y) * g_Lv[e1.x]
                         + __int_as_float(e2.y) * g_Lv[e2.x]
                         + __int_as_float(e3.y) * g_Lv[e3.x];
                }
                for (; k < cb1; k++) {
                    int2 e = g_pairC[k];
                    acc += __int_as_float(e.y) * g_Lv[e.x];
                }
                atomicAdd(&g_w[gtid], -acc);
                dD -= (double)acc * (double)r_reg;
            }
            if (tid < MPB) {
                int ind = locInd[m];
                float pn[9], acc9[9];
                #pragma unroll
                for (int j = 0; j < 9; j++) { pn[j] = g_r[ind + OFF9(j)]; acc9[j] = 0.f; }
                #pragma unroll
                for (int i9 = 0; i9 < 9; i9++) {
                    #pragma unroll
                    for (int j9 = i9; j9 < 9; j9++) {
                        float v = g_S45[TIDX(i9, j9) * NLOC + m];
                        acc9[i9] += v * pn[j9];
                        if (j9 > i9) acc9[j9] += v * pn[i9];
                    }
                }
                #pragma unroll
                for (int i9 = 0; i9 < 9; i9++) {
                    atomicAdd(&g_w[ind + OFF9(i9)], -acc9[i9]);
                    dD -= (double)acc9[i9] * (double)pn[i9];
                }
                int ind2 = iuInd[m];
                float rind = g_r[ind2];
                float acc2 = 0.f;
                #pragma unroll
                for (int l = 0; l < KIU; l++) {
                    float wv = g_Wiu[l * NLOC + m];
                    int nb   = g_iuNbT[l * NLOC + m];
                    float rnb = g_r[nb];
                    acc2 += wv * rnb;
                    atomicAdd(&g_w[nb], -wv * rind);
                    dD -= (double)(wv * rind) * (double)rnb;
                }
                atomicAdd(&g_w[ind2], -acc2);
                dD -= (double)acc2 * (double)rind;
            }
            dD = bred(dD, sred);
            if (tid == 0) g_dotD2[blockIdx.x] = dD;
        }
        gbar(ep);

        // Phase U: reduce gamma/delta; alpha,beta; register-resident update
        {
            double gamma = 0.0, delta = 0.0;
            if (tid < NBLK) {
                double2 gd = g_dotGD[tid];
                gamma = gd.x;
                delta = gd.y + g_dotD2[tid];
            }
            double2 gd = bred2(gamma, delta, sm2);
            if (tid == 0) {
                gamma = gd.x; delta = gd.y;
                double beta, alpha;
                if (it == 0) {
                    beta = 0.0;
                    alpha = gamma / delta;
                } else {
                    beta = gamma / s_gamma_prev;
                    alpha = gamma / (delta - beta * gamma / s_alpha_prev);
                }
                s_alpha = alpha; s_beta = beta;
                s_gamma_prev = gamma; s_alpha_prev = alpha;
            }
            __syncthreads();
            float alpha = (float)s_alpha;
            float beta  = (float)s_beta;
            float wi = g_w[gtid];
            if (it == 0) { p_reg = r_reg; s_reg = wi; }
            else {
                p_reg = r_reg + beta * p_reg;
                s_reg = wi + beta * s_reg;
            }
            x_reg += alpha * p_reg;
            r_reg = r_reg - alpha * s_reg;
            g_r[gtid] = r_reg;
            if (it == CG_STEPS - 1) x[gtid] = x_reg;
        }
        if (it + 1 < CG_STEPS) gbar(ep);
    }

    // ---- exit: last block past the final barrier resets barrier state
    __syncthreads();
    if (tid == 0) {
        __threadfence();
        if (atomicAdd(&g_exit, 1u) == NBLK - 1) {
            g_exit = 0u;
            g_sense = 0u;     // g_count already self-reset to 0
            __threadfence();
        }
    }
}

// ---------------- host launch ----------------
extern "C" void kernel_launch(void* const* d_in, const int* in_sizes, int n_in,
                              void* d_out, int out_size) {
    const float* CMw    = (const float*)d_in[0];
    const float* LOCw   = (const float*)d_in[1];
    const float* IUw    = (const float*)d_in[2];
    const float* KUw    = (const float*)d_in[3];
    const float* lmbda  = (const float*)d_in[4];
    const float* kToUcf = (const float*)d_in[5];
    const float* known  = (const float*)d_in[6];
    const float* kToU   = (const float*)d_in[7];
    const float* Wd     = (const float*)d_in[8];
    const float* LF     = (const float*)d_in[9];
    const float* IUf    = (const float*)d_in[10];
    const int*   wrow   = (const int*)d_in[11];
    const int*   wcol   = (const int*)d_in[12];
    const int*   locInd = (const int*)d_in[13];
    const int*   iuInd  = (const int*)d_in[14];
    const int*   iuNb   = (const int*)d_in[15];
    float* x = (float*)d_out;

    k_all<<<NBLK, TPB>>>(x, CMw, LOCw, IUw, KUw, lmbda, kToUcf, known, kToU,
                         Wd, LF, IUf, wrow, wcol, locInd, iuInd, iuNb);
}